// round 16
// baseline (speedup 1.0000x reference)
#include <cuda_runtime.h>
#include <cuda_fp16.h>
#include <cstdint>

// LightGCN propagation: N=100000, E=1600000, D=64, L=3.
// out = (x0 + x1 + x2 + x3)/4, x_{l+1} = A_norm @ x_l (with self loops).
//
// R16: R15 core (HFMA2 inner body + batch-2 gather pipeline, fixed-stride CSR,
// z-recurrence) + DEGREE-SORTED node scheduling: counting sort by in-degree
// (65 bins) so the 4 nodes sharing a warp have near-equal trip counts --
// removes the ~25-30% padded iterations of maxm = max(m over 4 Poisson(16)).
//   z_{l+1}[d] = dinv[d]^2 * ( z_l[d] + sum_e w_e * z_l[src_e] )

#define NN 100000
#define EE 1600000
#define DD 64
#define ND (NN * DD)       // 6,400,000 floats
#define ND8 (ND / 8)       // 800,000 uint4 (fp16 rows)
#define CSTRIDE 64         // fixed CSR bucket stride (max indeg ~45)
#define NBINS (CSTRIDE + 1)

// Scratch (allocation-free: __device__ globals)
__device__ int g_is32;
__device__ int g_deg[NN];             // src-occurrence count (excl. self loop)
__device__ int g_indeg[NN];           // dst in-degree (excl. self loop)
__device__ uint2 g_csr[NN * CSTRIDE]; // (src, half2(w,w) bits), slot dst*64+rank
__device__ int g_hbin[NBINS];         // degree histogram
__device__ int g_hcur[NBINS];         // scatter cursors
__device__ int g_order[NN];           // nodes sorted by in-degree
__device__ uint4 g_z0[ND8];           // z0 = dinv*emb, 8 halves per uint4
__device__ uint4 g_z1[ND8];           // z1
__device__ uint4 g_z2[ND8];           // z2

// ---------------------------------------------------------------------------
// Index-dtype detection (JAX w/o x64 demotes int64 -> int32; element counts
// are identical either way, so sample values to disambiguate).
// ---------------------------------------------------------------------------
__global__ void k_detect(const void* __restrict__ idx) {
    if (threadIdx.x == 0) {
        const long long* p = (const long long*)idx;
        int is64 = 1;
        for (int k = 0; k < 256; k++) {
            long long v = p[k];
            if (v < 0 || v >= (long long)NN) { is64 = 0; break; }
        }
        g_is32 = !is64;
    }
}

// ---------------------------------------------------------------------------
// Fused count + fill: 4 edges per thread. deg histogram via RED (no return);
// CSR slot = dst*CSTRIDE + atomicAdd(indeg[dst]) return. w stored as
// half2(w,w) for the HFMA2 layer loop.
// ---------------------------------------------------------------------------
__global__ __launch_bounds__(256) void k_countfill(const void* __restrict__ idx,
                                                   const float* __restrict__ w) {
    int t = blockIdx.x * blockDim.x + threadIdx.x;
    int e = t * 4;
    if (e >= EE) return;
    int s0, s1, s2, s3, d0, d1, d2, d3;
    if (g_is32) {
        const int4* p = (const int4*)idx;
        int4 s = __ldg(&p[t]);
        int4 d = __ldg(&p[EE / 4 + t]);
        s0 = s.x; s1 = s.y; s2 = s.z; s3 = s.w;
        d0 = d.x; d1 = d.y; d2 = d.z; d3 = d.w;
    } else {
        const long long* p = (const long long*)idx;
        s0 = (int)p[e];      s1 = (int)p[e + 1];
        s2 = (int)p[e + 2];  s3 = (int)p[e + 3];
        d0 = (int)p[EE + e];     d1 = (int)p[EE + e + 1];
        d2 = (int)p[EE + e + 2]; d3 = (int)p[EE + e + 3];
    }
    atomicAdd(&g_deg[s0], 1); atomicAdd(&g_deg[s1], 1);
    atomicAdd(&g_deg[s2], 1); atomicAdd(&g_deg[s3], 1);
    float4 wv = __ldg((const float4*)(w + e));
    __half2 w0 = __half2half2(__float2half_rn(wv.x));
    __half2 w1 = __half2half2(__float2half_rn(wv.y));
    __half2 w2 = __half2half2(__float2half_rn(wv.z));
    __half2 w3 = __half2half2(__float2half_rn(wv.w));
    int r0 = atomicAdd(&g_indeg[d0], 1);
    int r1 = atomicAdd(&g_indeg[d1], 1);
    int r2 = atomicAdd(&g_indeg[d2], 1);
    int r3 = atomicAdd(&g_indeg[d3], 1);
    if (r0 < CSTRIDE) g_csr[d0 * CSTRIDE + r0] = make_uint2((unsigned)s0, *reinterpret_cast<unsigned*>(&w0));
    if (r1 < CSTRIDE) g_csr[d1 * CSTRIDE + r1] = make_uint2((unsigned)s1, *reinterpret_cast<unsigned*>(&w1));
    if (r2 < CSTRIDE) g_csr[d2 * CSTRIDE + r2] = make_uint2((unsigned)s2, *reinterpret_cast<unsigned*>(&w2));
    if (r3 < CSTRIDE) g_csr[d3 * CSTRIDE + r3] = make_uint2((unsigned)s3, *reinterpret_cast<unsigned*>(&w3));
}

// ---------------------------------------------------------------------------
// Convert emb -> z0 = dinv*emb (fp16) + degree histogram (first NN threads).
// ---------------------------------------------------------------------------
__global__ __launch_bounds__(256) void k_z0(const float4* __restrict__ emb4) {
    int t = blockIdx.x * blockDim.x + threadIdx.x;
    if (t < NN) {
        int c = g_indeg[t];
        if (c > CSTRIDE) c = CSTRIDE;
        atomicAdd(&g_hbin[c], 1);
    }
    if (t >= ND8) return;
    int node = t >> 3;
    float dv = rsqrtf((float)(g_deg[node] + 1));
    float4 va = __ldg(&emb4[t * 2]);
    float4 vb = __ldg(&emb4[t * 2 + 1]);
    __half2 h0 = __floats2half2_rn(dv * va.x, dv * va.y);
    __half2 h1 = __floats2half2_rn(dv * va.z, dv * va.w);
    __half2 h2 = __floats2half2_rn(dv * vb.x, dv * vb.y);
    __half2 h3 = __floats2half2_rn(dv * vb.z, dv * vb.w);
    uint4 pck;
    pck.x = *reinterpret_cast<unsigned*>(&h0);
    pck.y = *reinterpret_cast<unsigned*>(&h1);
    pck.z = *reinterpret_cast<unsigned*>(&h2);
    pck.w = *reinterpret_cast<unsigned*>(&h3);
    g_z0[t] = pck;
}

// Tiny exclusive scan of the 65-bin histogram (1 block).
__global__ void k_hscan() {
    __shared__ int sh[NBINS];
    int t = threadIdx.x;
    if (t < NBINS) sh[t] = g_hbin[t];
    __syncthreads();
    if (t == 0) {
        int acc = 0;
        for (int c = 0; c < NBINS; c++) {
            int v = sh[c];
            sh[c] = acc;
            acc += v;
        }
    }
    __syncthreads();
    if (t < NBINS) g_hcur[t] = sh[t];
}

// Scatter node ids into degree-sorted order.
__global__ __launch_bounds__(256) void k_order() {
    int i = blockIdx.x * blockDim.x + threadIdx.x;
    if (i >= NN) return;
    int c = g_indeg[i];
    if (c > CSTRIDE) c = CSTRIDE;
    int pos = atomicAdd(&g_hcur[c], 1);
    g_order[pos] = i;
}

// Unpack uint4 (8 halves) into 8 floats.
__device__ __forceinline__ void unpack8(uint4 r, float* f) {
    float2 p0 = __half22float2(*reinterpret_cast<__half2*>(&r.x));
    float2 p1 = __half22float2(*reinterpret_cast<__half2*>(&r.y));
    float2 p2 = __half22float2(*reinterpret_cast<__half2*>(&r.z));
    float2 p3 = __half22float2(*reinterpret_cast<__half2*>(&r.w));
    f[0] = p0.x; f[1] = p0.y; f[2] = p1.x; f[3] = p1.y;
    f[4] = p2.x; f[5] = p2.y; f[6] = p3.x; f[7] = p3.y;
}

// ---------------------------------------------------------------------------
// Layer kernel: 8-lane group per node (4 nodes/warp), nodes taken in
// DEGREE-SORTED order (g_order) so trip counts are warp-uniform with ~zero
// padding. Lane owns uint4 = 8 fp16 features (LDG.128 gathers); width-8 shfls
// serve all 4 groups; batch-2 pipeline; per-chunk HFMA2 accumulation flushed
// to fp32.
//   S = z_old[d] + sum_e w_e * z_old[src_e]
// mode 0/1: z_new[d] = half( dinv[d]^2 * S )
// mode 2:   out = (emb + rdinv*(z1 + z_old) + dinv*S) * 0.25   (z_old==z2)
// ---------------------------------------------------------------------------
__global__ __launch_bounds__(256) void k_layer(const uint4* __restrict__ zOld,
                                               uint4* __restrict__ zNew,
                                               const float4* __restrict__ emb4,
                                               const uint4* __restrict__ z1p,
                                               float4* __restrict__ out4,
                                               int mode) {
    int glane = threadIdx.x & 7;
    int slot = blockIdx.x * 32 + (threadIdx.x >> 3);  // sorted position
    int node = __ldg(&g_order[slot]);                 // broadcast within group

    int start = node * CSTRIDE;
    int m = g_indeg[node];
    if (m > CSTRIDE) m = CSTRIDE;
    float d = (float)(g_deg[node] + 1);
    float dv = rsqrtf(d);

    int o = node * 8 + glane;
    float a[8];
    unpack8(zOld[o], a);   // S starts at z_old[d]

    // Warp-uniform iteration bound (nearly tight after degree sort).
    int m1 = max(m, __shfl_xor_sync(0xFFFFFFFFu, m, 8));
    int maxm = max(m1, __shfl_xor_sync(0xFFFFFFFFu, m1, 16));

    for (int base = 0; base < maxm; base += 8) {
        uint2 ed = make_uint2(0u, 0u);
        if (base + glane < m) ed = __ldg(&g_csr[start + base + glane]);
        int t = maxm - base;
        if (t > 8) t = 8;

        // fp16 chunk accumulators (<= 8 terms each)
        unsigned zz = 0u;
        __half2 c0 = *reinterpret_cast<__half2*>(&zz);
        __half2 c1 = c0, c2 = c0, c3 = c0;

        int j = 0;
        for (; j + 2 <= t; j += 2) {
            unsigned sj0 = __shfl_sync(0xFFFFFFFFu, ed.x, j, 8);
            unsigned wb0 = __shfl_sync(0xFFFFFFFFu, ed.y, j, 8);
            unsigned sj1 = __shfl_sync(0xFFFFFFFFu, ed.x, j + 1, 8);
            unsigned wb1 = __shfl_sync(0xFFFFFFFFu, ed.y, j + 1, 8);
            uint4 vr0 = __ldg(&zOld[sj0 * 8 + glane]);
            uint4 vr1 = __ldg(&zOld[sj1 * 8 + glane]);
            __half2 wh0 = *reinterpret_cast<__half2*>(&wb0);
            __half2 wh1 = *reinterpret_cast<__half2*>(&wb1);
            c0 = __hfma2(wh0, *reinterpret_cast<__half2*>(&vr0.x), c0);
            c1 = __hfma2(wh0, *reinterpret_cast<__half2*>(&vr0.y), c1);
            c2 = __hfma2(wh0, *reinterpret_cast<__half2*>(&vr0.z), c2);
            c3 = __hfma2(wh0, *reinterpret_cast<__half2*>(&vr0.w), c3);
            c0 = __hfma2(wh1, *reinterpret_cast<__half2*>(&vr1.x), c0);
            c1 = __hfma2(wh1, *reinterpret_cast<__half2*>(&vr1.y), c1);
            c2 = __hfma2(wh1, *reinterpret_cast<__half2*>(&vr1.z), c2);
            c3 = __hfma2(wh1, *reinterpret_cast<__half2*>(&vr1.w), c3);
        }
        if (j < t) {
            unsigned sj = __shfl_sync(0xFFFFFFFFu, ed.x, j, 8);
            unsigned wb = __shfl_sync(0xFFFFFFFFu, ed.y, j, 8);
            uint4 vr = __ldg(&zOld[sj * 8 + glane]);
            __half2 wh = *reinterpret_cast<__half2*>(&wb);
            c0 = __hfma2(wh, *reinterpret_cast<__half2*>(&vr.x), c0);
            c1 = __hfma2(wh, *reinterpret_cast<__half2*>(&vr.y), c1);
            c2 = __hfma2(wh, *reinterpret_cast<__half2*>(&vr.z), c2);
            c3 = __hfma2(wh, *reinterpret_cast<__half2*>(&vr.w), c3);
        }

        // Flush chunk to fp32
        float2 q0 = __half22float2(c0);
        float2 q1 = __half22float2(c1);
        float2 q2 = __half22float2(c2);
        float2 q3 = __half22float2(c3);
        a[0] += q0.x; a[1] += q0.y; a[2] += q1.x; a[3] += q1.y;
        a[4] += q2.x; a[5] += q2.y; a[6] += q3.x; a[7] += q3.y;
    }

    if (mode != 2) {
        float s2 = dv * dv;
        __half2 h0 = __floats2half2_rn(s2 * a[0], s2 * a[1]);
        __half2 h1 = __floats2half2_rn(s2 * a[2], s2 * a[3]);
        __half2 h2 = __floats2half2_rn(s2 * a[4], s2 * a[5]);
        __half2 h3 = __floats2half2_rn(s2 * a[6], s2 * a[7]);
        uint4 wv;
        wv.x = *reinterpret_cast<unsigned*>(&h0);
        wv.y = *reinterpret_cast<unsigned*>(&h1);
        wv.z = *reinterpret_cast<unsigned*>(&h2);
        wv.w = *reinterpret_cast<unsigned*>(&h3);
        zNew[o] = wv;
    } else {
        float rv = d * dv;  // sqrt(d) = d * rsqrt(d)
        float v0[8];
        unpack8(__ldg(&zOld[o]), v0);   // reload (L1-hot) — saves live regs
        float z1f[8];
        unpack8(__ldg(&z1p[o]), z1f);
        float4 ea = __ldg(&emb4[o * 2]);
        float4 eb = __ldg(&emb4[o * 2 + 1]);
        // x1 = rdinv*z1, x2 = rdinv*z2(=v0), x3 = dinv*S
        float4 oa, ob;
        oa.x = (ea.x + rv * (z1f[0] + v0[0]) + dv * a[0]) * 0.25f;
        oa.y = (ea.y + rv * (z1f[1] + v0[1]) + dv * a[1]) * 0.25f;
        oa.z = (ea.z + rv * (z1f[2] + v0[2]) + dv * a[2]) * 0.25f;
        oa.w = (ea.w + rv * (z1f[3] + v0[3]) + dv * a[3]) * 0.25f;
        ob.x = (eb.x + rv * (z1f[4] + v0[4]) + dv * a[4]) * 0.25f;
        ob.y = (eb.y + rv * (z1f[5] + v0[5]) + dv * a[5]) * 0.25f;
        ob.z = (eb.z + rv * (z1f[6] + v0[6]) + dv * a[6]) * 0.25f;
        ob.w = (eb.w + rv * (z1f[7] + v0[7]) + dv * a[7]) * 0.25f;
        out4[o * 2] = oa;
        out4[o * 2 + 1] = ob;
    }
}

// ---------------------------------------------------------------------------
extern "C" void kernel_launch(void* const* d_in, const int* in_sizes, int n_in,
                              void* d_out, int out_size) {
    // Bind inputs by unique element count (robust to metadata ordering).
    const float* emb = nullptr;   // 6,400,000 f32
    const float* ew = nullptr;    // 1,600,000 f32
    const void* idx = nullptr;    // 3,200,000 elems (int32 or int64, detected)
    for (int i = 0; i < n_in; i++) {
        if (in_sizes[i] == ND) emb = (const float*)d_in[i];
        else if (in_sizes[i] == EE) ew = (const float*)d_in[i];
        else if (in_sizes[i] == 2 * EE) idx = d_in[i];
    }
    if (!emb) emb = (const float*)d_in[0];
    if (!ew) ew = (const float*)d_in[1];
    if (!idx) idx = d_in[2];

    float4* out4 = (float4*)d_out;

    uint4* z0;
    uint4* z1;
    uint4* z2;
    int* degp;
    int* indegp;
    int* hbinp;
    cudaGetSymbolAddress((void**)&z0, g_z0);
    cudaGetSymbolAddress((void**)&z1, g_z1);
    cudaGetSymbolAddress((void**)&z2, g_z2);
    cudaGetSymbolAddress((void**)&degp, g_deg);
    cudaGetSymbolAddress((void**)&indegp, g_indeg);
    cudaGetSymbolAddress((void**)&hbinp, g_hbin);

    const int T = 256;
    const int gN = (NN + T - 1) / T;            // 391
    const int gC = (ND8 + T - 1) / T;           // 3125
    const int gE4 = (EE / 4 + T - 1) / T;       // 1563
    const int gL = NN / 32;                     // 3125 (32 nodes/block)

    // Precompute: zero histograms, detect dtype, fused count+fill,
    // z0 convert + degree histogram, 65-bin scan, degree-sorted order.
    cudaMemsetAsync(degp, 0, NN * sizeof(int));
    cudaMemsetAsync(indegp, 0, NN * sizeof(int));
    cudaMemsetAsync(hbinp, 0, NBINS * sizeof(int));
    k_detect<<<1, 32>>>(idx);
    k_countfill<<<gE4, T>>>(idx, ew);
    k_z0<<<gC, T>>>((const float4*)emb);
    k_hscan<<<1, 128>>>();
    k_order<<<gN, T>>>();

    // Layer 1: z1 <- dinv^2 (z0 + A_w z0)
    k_layer<<<gL, T>>>(z0, z1, nullptr, nullptr, nullptr, 0);
    // Layer 2: z2
    k_layer<<<gL, T>>>(z1, z2, nullptr, nullptr, nullptr, 1);
    // Layer 3: out = (x0 + x1 + x2 + x3) / 4  (fp32 out)
    k_layer<<<gL, T>>>(z2, nullptr, (const float4*)emb, z1, out4, 2);
}

// round 17
// speedup vs baseline: 1.3773x; 1.3773x over previous
#include <cuda_runtime.h>
#include <cuda_fp16.h>
#include <cstdint>

// LightGCN propagation: N=100000, E=1600000, D=64, L=3.
// out = (x0 + x1 + x2 + x3)/4, x_{l+1} = A_norm @ x_l (with self loops).
//
// R17: R15 core exactly (HFMA2 inner body + batch-2 gather pipeline,
// fixed-stride CSR, z-recurrence, CONTIGUOUS node order — R16's degree sort
// destroyed CSR/z locality and regressed). Overhead strip: dtype detection
// inlined into k_countfill at warp level (no k_detect launch; ~5us/launch
// measured), deg+indeg merged into one array (one memset node).
//   z_{l+1}[d] = dinv[d]^2 * ( z_l[d] + sum_e w_e * z_l[src_e] )

#define NN 100000
#define EE 1600000
#define DD 64
#define ND (NN * DD)       // 6,400,000 floats
#define ND8 (ND / 8)       // 800,000 uint4 (fp16 rows)
#define CSTRIDE 64         // fixed CSR bucket stride (max indeg ~45)

// Scratch (allocation-free: __device__ globals)
__device__ int g_cnt[2 * NN];         // [0,NN): src deg; [NN,2NN): dst indeg
__device__ uint2 g_csr[NN * CSTRIDE]; // (src, half2(w,w) bits), slot dst*64+rank
__device__ uint4 g_z0[ND8];           // z0 = dinv*emb, 8 halves per uint4
__device__ uint4 g_z1[ND8];           // z1
__device__ uint4 g_z2[ND8];           // z2

// ---------------------------------------------------------------------------
// Warp-level index-dtype detection (JAX w/o x64 demotes int64 -> int32;
// element counts are identical either way). Lane L samples element L as
// int64; for int32 data the fused high word is a random index (nonzero w.p.
// ~1-1e-5), so all-32-in-range <=> genuinely int64. No launch, no race:
// every warp computes the same answer independently.
// ---------------------------------------------------------------------------
__device__ __forceinline__ int detect_is32(const void* idx) {
    const long long* p = (const long long*)idx;
    long long v = p[threadIdx.x & 31];
    int ok = (v >= 0 && v < (long long)NN);
    return !__all_sync(0xFFFFFFFFu, ok);
}

// ---------------------------------------------------------------------------
// Fused count + fill: 4 edges per thread. deg histogram via RED (no return);
// CSR slot = dst*CSTRIDE + atomicAdd(indeg[dst]) return. w stored as
// half2(w,w) for the HFMA2 layer loop.
// ---------------------------------------------------------------------------
__global__ __launch_bounds__(256) void k_countfill(const void* __restrict__ idx,
                                                   const float* __restrict__ w) {
    int is32 = detect_is32(idx);
    int t = blockIdx.x * blockDim.x + threadIdx.x;
    int e = t * 4;
    if (e >= EE) return;
    int s0, s1, s2, s3, d0, d1, d2, d3;
    if (is32) {
        const int4* p = (const int4*)idx;
        int4 s = __ldg(&p[t]);
        int4 d = __ldg(&p[EE / 4 + t]);
        s0 = s.x; s1 = s.y; s2 = s.z; s3 = s.w;
        d0 = d.x; d1 = d.y; d2 = d.z; d3 = d.w;
    } else {
        const long long* p = (const long long*)idx;
        s0 = (int)p[e];      s1 = (int)p[e + 1];
        s2 = (int)p[e + 2];  s3 = (int)p[e + 3];
        d0 = (int)p[EE + e];     d1 = (int)p[EE + e + 1];
        d2 = (int)p[EE + e + 2]; d3 = (int)p[EE + e + 3];
    }
    atomicAdd(&g_cnt[s0], 1); atomicAdd(&g_cnt[s1], 1);
    atomicAdd(&g_cnt[s2], 1); atomicAdd(&g_cnt[s3], 1);
    float4 wv = __ldg((const float4*)(w + e));
    __half2 w0 = __half2half2(__float2half_rn(wv.x));
    __half2 w1 = __half2half2(__float2half_rn(wv.y));
    __half2 w2 = __half2half2(__float2half_rn(wv.z));
    __half2 w3 = __half2half2(__float2half_rn(wv.w));
    int r0 = atomicAdd(&g_cnt[NN + d0], 1);
    int r1 = atomicAdd(&g_cnt[NN + d1], 1);
    int r2 = atomicAdd(&g_cnt[NN + d2], 1);
    int r3 = atomicAdd(&g_cnt[NN + d3], 1);
    if (r0 < CSTRIDE) g_csr[d0 * CSTRIDE + r0] = make_uint2((unsigned)s0, *reinterpret_cast<unsigned*>(&w0));
    if (r1 < CSTRIDE) g_csr[d1 * CSTRIDE + r1] = make_uint2((unsigned)s1, *reinterpret_cast<unsigned*>(&w1));
    if (r2 < CSTRIDE) g_csr[d2 * CSTRIDE + r2] = make_uint2((unsigned)s2, *reinterpret_cast<unsigned*>(&w2));
    if (r3 < CSTRIDE) g_csr[d3 * CSTRIDE + r3] = make_uint2((unsigned)s3, *reinterpret_cast<unsigned*>(&w3));
}

// ---------------------------------------------------------------------------
// Convert emb -> z0 = dinv*emb (fp16, uint4 granularity); dinv inline from deg.
// ---------------------------------------------------------------------------
__global__ __launch_bounds__(256) void k_z0(const float4* __restrict__ emb4) {
    int t = blockIdx.x * blockDim.x + threadIdx.x;
    if (t >= ND8) return;
    int node = t >> 3;
    float dv = rsqrtf((float)(g_cnt[node] + 1));
    float4 va = __ldg(&emb4[t * 2]);
    float4 vb = __ldg(&emb4[t * 2 + 1]);
    __half2 h0 = __floats2half2_rn(dv * va.x, dv * va.y);
    __half2 h1 = __floats2half2_rn(dv * va.z, dv * va.w);
    __half2 h2 = __floats2half2_rn(dv * vb.x, dv * vb.y);
    __half2 h3 = __floats2half2_rn(dv * vb.z, dv * vb.w);
    uint4 pck;
    pck.x = *reinterpret_cast<unsigned*>(&h0);
    pck.y = *reinterpret_cast<unsigned*>(&h1);
    pck.z = *reinterpret_cast<unsigned*>(&h2);
    pck.w = *reinterpret_cast<unsigned*>(&h3);
    g_z0[t] = pck;
}

// Unpack uint4 (8 halves) into 8 floats.
__device__ __forceinline__ void unpack8(uint4 r, float* f) {
    float2 p0 = __half22float2(*reinterpret_cast<__half2*>(&r.x));
    float2 p1 = __half22float2(*reinterpret_cast<__half2*>(&r.y));
    float2 p2 = __half22float2(*reinterpret_cast<__half2*>(&r.z));
    float2 p3 = __half22float2(*reinterpret_cast<__half2*>(&r.w));
    f[0] = p0.x; f[1] = p0.y; f[2] = p1.x; f[3] = p1.y;
    f[4] = p2.x; f[5] = p2.y; f[6] = p3.x; f[7] = p3.y;
}

// ---------------------------------------------------------------------------
// Layer kernel: 8-lane group per node (4 nodes/warp, CONTIGUOUS node ids),
// lane owns uint4 = 8 fp16 features (LDG.128 gathers), width-8 shfls serve
// all 4 groups. Batch-2 gather pipeline + per-chunk fp16 HFMA2 accumulation
// (<=8 terms) flushed to fp32.
//   S = z_old[d] + sum_e w_e * z_old[src_e]
// mode 0/1: z_new[d] = half( dinv[d]^2 * S )
// mode 2:   out = (emb + rdinv*(z1 + z_old) + dinv*S) * 0.25   (z_old==z2)
// ---------------------------------------------------------------------------
__global__ __launch_bounds__(256) void k_layer(const uint4* __restrict__ zOld,
                                               uint4* __restrict__ zNew,
                                               const float4* __restrict__ emb4,
                                               const uint4* __restrict__ z1p,
                                               float4* __restrict__ out4,
                                               int mode) {
    int glane = threadIdx.x & 7;
    int node = blockIdx.x * 32 + (threadIdx.x >> 3);  // grid covers exactly NN

    int start = node * CSTRIDE;
    int m = g_cnt[NN + node];
    if (m > CSTRIDE) m = CSTRIDE;
    float d = (float)(g_cnt[node] + 1);
    float dv = rsqrtf(d);

    int o = node * 8 + glane;
    float a[8];
    unpack8(zOld[o], a);   // S starts at z_old[d]

    // Warp-uniform iteration bound across the 4 groups in this warp.
    int m1 = max(m, __shfl_xor_sync(0xFFFFFFFFu, m, 8));
    int maxm = max(m1, __shfl_xor_sync(0xFFFFFFFFu, m1, 16));

    for (int base = 0; base < maxm; base += 8) {
        uint2 ed = make_uint2(0u, 0u);
        if (base + glane < m) ed = __ldg(&g_csr[start + base + glane]);
        int t = maxm - base;
        if (t > 8) t = 8;

        // fp16 chunk accumulators (<= 8 terms each)
        unsigned zz = 0u;
        __half2 c0 = *reinterpret_cast<__half2*>(&zz);
        __half2 c1 = c0, c2 = c0, c3 = c0;

        int j = 0;
        for (; j + 2 <= t; j += 2) {
            unsigned sj0 = __shfl_sync(0xFFFFFFFFu, ed.x, j, 8);
            unsigned wb0 = __shfl_sync(0xFFFFFFFFu, ed.y, j, 8);
            unsigned sj1 = __shfl_sync(0xFFFFFFFFu, ed.x, j + 1, 8);
            unsigned wb1 = __shfl_sync(0xFFFFFFFFu, ed.y, j + 1, 8);
            uint4 vr0 = __ldg(&zOld[sj0 * 8 + glane]);
            uint4 vr1 = __ldg(&zOld[sj1 * 8 + glane]);
            __half2 wh0 = *reinterpret_cast<__half2*>(&wb0);
            __half2 wh1 = *reinterpret_cast<__half2*>(&wb1);
            c0 = __hfma2(wh0, *reinterpret_cast<__half2*>(&vr0.x), c0);
            c1 = __hfma2(wh0, *reinterpret_cast<__half2*>(&vr0.y), c1);
            c2 = __hfma2(wh0, *reinterpret_cast<__half2*>(&vr0.z), c2);
            c3 = __hfma2(wh0, *reinterpret_cast<__half2*>(&vr0.w), c3);
            c0 = __hfma2(wh1, *reinterpret_cast<__half2*>(&vr1.x), c0);
            c1 = __hfma2(wh1, *reinterpret_cast<__half2*>(&vr1.y), c1);
            c2 = __hfma2(wh1, *reinterpret_cast<__half2*>(&vr1.z), c2);
            c3 = __hfma2(wh1, *reinterpret_cast<__half2*>(&vr1.w), c3);
        }
        if (j < t) {
            unsigned sj = __shfl_sync(0xFFFFFFFFu, ed.x, j, 8);
            unsigned wb = __shfl_sync(0xFFFFFFFFu, ed.y, j, 8);
            uint4 vr = __ldg(&zOld[sj * 8 + glane]);
            __half2 wh = *reinterpret_cast<__half2*>(&wb);
            c0 = __hfma2(wh, *reinterpret_cast<__half2*>(&vr.x), c0);
            c1 = __hfma2(wh, *reinterpret_cast<__half2*>(&vr.y), c1);
            c2 = __hfma2(wh, *reinterpret_cast<__half2*>(&vr.z), c2);
            c3 = __hfma2(wh, *reinterpret_cast<__half2*>(&vr.w), c3);
        }

        // Flush chunk to fp32
        float2 q0 = __half22float2(c0);
        float2 q1 = __half22float2(c1);
        float2 q2 = __half22float2(c2);
        float2 q3 = __half22float2(c3);
        a[0] += q0.x; a[1] += q0.y; a[2] += q1.x; a[3] += q1.y;
        a[4] += q2.x; a[5] += q2.y; a[6] += q3.x; a[7] += q3.y;
    }

    if (mode != 2) {
        float s2 = dv * dv;
        __half2 h0 = __floats2half2_rn(s2 * a[0], s2 * a[1]);
        __half2 h1 = __floats2half2_rn(s2 * a[2], s2 * a[3]);
        __half2 h2 = __floats2half2_rn(s2 * a[4], s2 * a[5]);
        __half2 h3 = __floats2half2_rn(s2 * a[6], s2 * a[7]);
        uint4 wv;
        wv.x = *reinterpret_cast<unsigned*>(&h0);
        wv.y = *reinterpret_cast<unsigned*>(&h1);
        wv.z = *reinterpret_cast<unsigned*>(&h2);
        wv.w = *reinterpret_cast<unsigned*>(&h3);
        zNew[o] = wv;
    } else {
        float rv = d * dv;  // sqrt(d) = d * rsqrt(d)
        float v0[8];
        unpack8(__ldg(&zOld[o]), v0);   // reload (L1-hot) — saves live regs
        float z1f[8];
        unpack8(__ldg(&z1p[o]), z1f);
        float4 ea = __ldg(&emb4[o * 2]);
        float4 eb = __ldg(&emb4[o * 2 + 1]);
        // x1 = rdinv*z1, x2 = rdinv*z2(=v0), x3 = dinv*S
        float4 oa, ob;
        oa.x = (ea.x + rv * (z1f[0] + v0[0]) + dv * a[0]) * 0.25f;
        oa.y = (ea.y + rv * (z1f[1] + v0[1]) + dv * a[1]) * 0.25f;
        oa.z = (ea.z + rv * (z1f[2] + v0[2]) + dv * a[2]) * 0.25f;
        oa.w = (ea.w + rv * (z1f[3] + v0[3]) + dv * a[3]) * 0.25f;
        ob.x = (eb.x + rv * (z1f[4] + v0[4]) + dv * a[4]) * 0.25f;
        ob.y = (eb.y + rv * (z1f[5] + v0[5]) + dv * a[5]) * 0.25f;
        ob.z = (eb.z + rv * (z1f[6] + v0[6]) + dv * a[6]) * 0.25f;
        ob.w = (eb.w + rv * (z1f[7] + v0[7]) + dv * a[7]) * 0.25f;
        out4[o * 2] = oa;
        out4[o * 2 + 1] = ob;
    }
}

// ---------------------------------------------------------------------------
extern "C" void kernel_launch(void* const* d_in, const int* in_sizes, int n_in,
                              void* d_out, int out_size) {
    // Bind inputs by unique element count (robust to metadata ordering).
    const float* emb = nullptr;   // 6,400,000 f32
    const float* ew = nullptr;    // 1,600,000 f32
    const void* idx = nullptr;    // 3,200,000 elems (int32 or int64, detected)
    for (int i = 0; i < n_in; i++) {
        if (in_sizes[i] == ND) emb = (const float*)d_in[i];
        else if (in_sizes[i] == EE) ew = (const float*)d_in[i];
        else if (in_sizes[i] == 2 * EE) idx = d_in[i];
    }
    if (!emb) emb = (const float*)d_in[0];
    if (!ew) ew = (const float*)d_in[1];
    if (!idx) idx = d_in[2];

    float4* out4 = (float4*)d_out;

    uint4* z0;
    uint4* z1;
    uint4* z2;
    int* cntp;
    cudaGetSymbolAddress((void**)&z0, g_z0);
    cudaGetSymbolAddress((void**)&z1, g_z1);
    cudaGetSymbolAddress((void**)&z2, g_z2);
    cudaGetSymbolAddress((void**)&cntp, g_cnt);

    const int T = 256;
    const int gC = (ND8 + T - 1) / T;           // 3125
    const int gE4 = (EE / 4 + T - 1) / T;       // 1563
    const int gL = NN / 32;                     // 3125 (32 nodes/block)

    // Precompute: one memset (deg+indeg), fused count+fill (detect inlined),
    // z0 convert. 3 graph nodes before the layers.
    cudaMemsetAsync(cntp, 0, 2 * NN * sizeof(int));
    k_countfill<<<gE4, T>>>(idx, ew);
    k_z0<<<gC, T>>>((const float4*)emb);

    // Layer 1: z1 <- dinv^2 (z0 + A_w z0)
    k_layer<<<gL, T>>>(z0, z1, nullptr, nullptr, nullptr, 0);
    // Layer 2: z2
    k_layer<<<gL, T>>>(z1, z2, nullptr, nullptr, nullptr, 1);
    // Layer 3: out = (x0 + x1 + x2 + x3) / 4  (fp32 out)
    k_layer<<<gL, T>>>(z2, nullptr, (const float4*)emb, z1, out4, 2);
}